// round 1
// baseline (speedup 1.0000x reference)
#include <cuda_runtime.h>
#include <cuda_bf16.h>
#include <cstdint>

// MeanAggregator: out[i, :] = mean over e in [0,EPN) of features[edge_dst[i*EPN + e], :]
// D = 128 floats per row. One warp per output node; lane l owns float4 columns [4l, 4l+4).
// Feature table (51.2 MB) fits in L2 -> L2-bandwidth-bound gather.

#define D_DIM 128
#define VEC_PER_LANE 1   // each lane: one float4 (32 lanes * 4 = 128)

// Fast path: compile-time EPN, fully unrolled -> 17 independent LDG.128 per lane (MLP=17).
template <int EPN>
__global__ __launch_bounds__(256) void mean_agg_kernel_fixed(
    const float* __restrict__ feat,
    const int*   __restrict__ edge_dst,
    float*       __restrict__ out,
    int B)
{
    const int warp = (blockIdx.x * blockDim.x + threadIdx.x) >> 5;
    const int lane = threadIdx.x & 31;
    if (warp >= B) return;

    const int* __restrict__ idx = edge_dst + (size_t)warp * EPN;

    float4 acc = make_float4(0.f, 0.f, 0.f, 0.f);

#pragma unroll
    for (int e = 0; e < EPN; ++e) {
        const int nb = __ldg(idx + e);
        const float4 v = __ldg(reinterpret_cast<const float4*>(
                                   feat + (size_t)nb * D_DIM) + lane);
        acc.x += v.x; acc.y += v.y; acc.z += v.z; acc.w += v.w;
    }

    const float inv = 1.0f / (float)EPN;
    acc.x *= inv; acc.y *= inv; acc.z *= inv; acc.w *= inv;

    reinterpret_cast<float4*>(out + (size_t)warp * D_DIM)[lane] = acc;
}

// General fallback: runtime EPN.
__global__ __launch_bounds__(256) void mean_agg_kernel_dyn(
    const float* __restrict__ feat,
    const int*   __restrict__ edge_dst,
    float*       __restrict__ out,
    int B, int epn)
{
    const int warp = (blockIdx.x * blockDim.x + threadIdx.x) >> 5;
    const int lane = threadIdx.x & 31;
    if (warp >= B) return;

    const int* __restrict__ idx = edge_dst + (size_t)warp * epn;

    float4 acc = make_float4(0.f, 0.f, 0.f, 0.f);

#pragma unroll 4
    for (int e = 0; e < epn; ++e) {
        const int nb = __ldg(idx + e);
        const float4 v = __ldg(reinterpret_cast<const float4*>(
                                   feat + (size_t)nb * D_DIM) + lane);
        acc.x += v.x; acc.y += v.y; acc.z += v.z; acc.w += v.w;
    }

    const float inv = 1.0f / (float)epn;
    acc.x *= inv; acc.y *= inv; acc.z *= inv; acc.w *= inv;

    reinterpret_cast<float4*>(out + (size_t)warp * D_DIM)[lane] = acc;
}

extern "C" void kernel_launch(void* const* d_in, const int* in_sizes, int n_in,
                              void* d_out, int out_size)
{
    // Inputs (metadata order): features [N_TOTAL*D] f32, edge_seg [E] i32,
    //                          edge_dst [E] i32, num_nodes scalar i32.
    const float* feat     = (const float*)d_in[0];
    const int*   edge_dst = (const int*)d_in[2];
    float*       out      = (float*)d_out;

    const int B   = out_size / D_DIM;          // 50000
    const int E   = in_sizes[2];               // 850000
    const int epn = E / B;                     // 17

    const int threads = 256;                   // 8 warps/block
    const int blocks  = (B * 32 + threads - 1) / threads;

    if (epn == 17) {
        mean_agg_kernel_fixed<17><<<blocks, threads>>>(feat, edge_dst, out, B);
    } else {
        mean_agg_kernel_dyn<<<blocks, threads>>>(feat, edge_dst, out, B, epn);
    }
}